// round 11
// baseline (speedup 1.0000x reference)
#include <cuda_runtime.h>
#include <cuda_bf16.h>
#include <cstdint>

// Koopman rollout via warp-level HMMA, register-resident weights, group-pipelined.
// 128 CTAs x 8 warps; CTA owns 32 rows (2 row-groups x 16). Warp e owns feature
// eighth e for BOTH groups (B-frags in 112 regs, loaded once via ldmatrix).
// Time loop is software-pipelined over row-groups: each barrier section runs
// MMA2(g) and MMA1(g') as independent chains plus the g-epilogue.
// Transcendentals replaced by degree-3 Taylor polys (|arg| <= ~0.02).

#define SMEM_BYTES 148992u
#define OFF_W1  0u        // [192 n][k stride 400B bf16]   76800 B (init staging)
#define OFF_W2C 76800u    // [128 n][k stride 272B]        34816 B (init staging)
#define OFF_W2R 111616u   // [64 n][k stride 144B]          9216 B (init staging)
#define OFF_B1  120832u   // f32[192]
#define OFF_B2  121600u   // f32[192]
#define OFF_YB  122368u   // y frags: [2 grp][32 lane][52 u32]  13312 B
#define OFF_HB  135680u   // h1 frags: same                      13312 B

__device__ __forceinline__ unsigned smem_u32(const void* p) {
    unsigned a;
    asm("{ .reg .u64 t; cvta.to.shared.u64 t, %1; cvt.u32.u64 %0, t; }"
        : "=r"(a) : "l"(p));
    return a;
}
__device__ __forceinline__ unsigned pbf(float lo, float hi) {
    unsigned r;
    asm("cvt.rn.bf16x2.f32 %0, %1, %2;" : "=r"(r) : "f"(hi), "f"(lo));
    return r;
}
// exp(z) for tiny z, degree-3 Taylor
__device__ __forceinline__ float exp3(float z) {
    return 1.0f + z * (1.0f + z * (0.5f + z * 0.16666667f));
}

#define LDSM4(r0, r1, r2, r3, a) \
    asm volatile("ldmatrix.sync.aligned.m8n8.x4.shared.b16 {%0,%1,%2,%3}, [%4];" \
                 : "=r"(r0), "=r"(r1), "=r"(r2), "=r"(r3) : "r"(a))
#define LDSM2(r0, r1, a) \
    asm volatile("ldmatrix.sync.aligned.m8n8.x2.shared.b16 {%0,%1}, [%2];" \
                 : "=r"(r0), "=r"(r1) : "r"(a))

#define MMA(d, a0, a1, a2, a3, b0, b1) \
    asm volatile("mma.sync.aligned.m16n8k16.row.col.f32.bf16.bf16.f32 " \
                 "{%0,%1,%2,%3},{%4,%5,%6,%7},{%8,%9},{%0,%1,%2,%3};" \
                 : "+f"((d)[0]), "+f"((d)[1]), "+f"((d)[2]), "+f"((d)[3]) \
                 : "r"(a0), "r"(a1), "r"(a2), "r"(a3), "r"(b0), "r"(b1))

__global__ void __launch_bounds__(256, 1)
koopman_pl_kernel(const float* __restrict__ x,
                  const float* __restrict__ cW1, const float* __restrict__ cb1,
                  const float* __restrict__ cW2, const float* __restrict__ cb2,
                  const float* __restrict__ rW1, const float* __restrict__ rb1,
                  const float* __restrict__ rW2, const float* __restrict__ rb2,
                  float* __restrict__ out)
{
    extern __shared__ unsigned char smem[];
    const unsigned sb = smem_u32(smem);
    const int tid = threadIdx.x;
    const int lane = tid & 31;
    const int e = tid >> 5;            // feature eighth 0..7

    float* b1f = (float*)(smem + OFF_B1);
    float* b2f = (float*)(smem + OFF_B2);

    // ---- one-time: weights -> bf16 SMEM (staging for ldmatrix) ----
    for (int idx = tid; idx < 192 * 96; idx += 256) {
        int n = idx / 96, k = 2 * (idx - n * 96);
        const float* s = (n < 128) ? (cW1 + n * 192 + k) : (rW1 + (n - 128) * 192 + k);
        *(unsigned*)(smem + OFF_W1 + n * 400 + k * 2) = pbf(s[0], s[1]);
    }
    for (int idx = tid; idx < 128 * 64; idx += 256) {
        int n = idx >> 6, k = 2 * (idx & 63);
        *(unsigned*)(smem + OFF_W2C + n * 272 + k * 2) =
            pbf(cW2[n * 128 + k], cW2[n * 128 + k + 1]);
    }
    for (int idx = tid; idx < 64 * 32; idx += 256) {
        int n = idx >> 5, k = 2 * (idx & 31);
        *(unsigned*)(smem + OFF_W2R + n * 144 + k * 2) =
            pbf(rW2[n * 64 + k], rW2[n * 64 + k + 1]);
    }
    for (int i = tid; i < 192; i += 256) {
        b1f[i] = (i < 128) ? cb1[i] : rb1[i - 128];
        b2f[i] = (i < 128) ? cb2[i] : rb2[i - 128];
    }
    __syncthreads();

    // ---- per-lane constants ----
    const int colb = 2 * (lane & 3);
    const int lrow = (lane & 7) + ((lane >> 4) << 3);
    const unsigned lkb = ((lane >> 3) & 1) * 16;

    // ---- persistent B-fragments (weights) in registers ----
    unsigned B1[12][3][2], B2c[8][2][2], B2r[4][2];
    {
        const unsigned aW1  = sb + OFF_W1 + e * 9600 + lrow * 400 + lkb;
        const unsigned aW1t = sb + OFF_W1 + e * 9600 + 6400 + (lane & 7) * 400 + lkb;
        const unsigned aW2C = sb + OFF_W2C + e * 4352 + lrow * 272 + lkb;
        const unsigned aW2R = sb + OFF_W2R + e * 1152 + (lane & 7) * 144 + lkb;
#pragma unroll
        for (int k = 0; k < 12; ++k) {
            LDSM4(B1[k][0][0], B1[k][0][1], B1[k][1][0], B1[k][1][1], aW1 + k * 32);
            LDSM2(B1[k][2][0], B1[k][2][1], aW1t + k * 32);
        }
#pragma unroll
        for (int k = 0; k < 8; ++k)
            LDSM4(B2c[k][0][0], B2c[k][0][1], B2c[k][1][0], B2c[k][1][1], aW2C + k * 32);
#pragma unroll
        for (int k = 0; k < 4; ++k)
            LDSM2(B2r[k][0], B2r[k][1], aW2R + k * 32);
    }

    // ---- bias registers (b2 pre-scaled by DT for the poly args) ----
    float2 bc1[3], bc2s[2], br2s;
#pragma unroll
    for (int n = 0; n < 3; ++n) bc1[n] = *(const float2*)(b1f + 8 * (3 * e + n) + colb);
#pragma unroll
    for (int n = 0; n < 2; ++n) {
        float2 b = *(const float2*)(b2f + 8 * (2 * e + n) + colb);
        bc2s[n] = make_float2(0.01f * b.x, 0.01f * b.y);
    }
    {
        float2 b = *(const float2*)(b2f + 128 + 8 * e + colb);
        br2s = make_float2(0.01f * b.x, 0.01f * b.y);
    }

    // ---- frag exchange rows ----
    unsigned* ybg[2];
    unsigned* hbg[2];
#pragma unroll
    for (int g = 0; g < 2; ++g) {
        ybg[g] = (unsigned*)(smem + OFF_YB) + (g * 32 + lane) * 52;
        hbg[g] = (unsigned*)(smem + OFF_HB) + (g * 32 + lane) * 52;
    }

    // ---- y master state ----
    int rows[2];
    rows[0] = blockIdx.x * 32 + (lane >> 2);
    rows[1] = rows[0] + 16;
    float ymc[2][2][4];   // [tile n][group][r0c0, r0c1, r1c0, r1c1]
    float ymr[2][4];      // [group]
#pragma unroll
    for (int g = 0; g < 2; ++g) {
        const float* x0 = x + (size_t)rows[g] * 12288;
        const float* x1 = x0 + 8 * 12288;
#pragma unroll
        for (int n = 0; n < 2; ++n) {
            int col = 8 * (2 * e + n) + colb;
            float2 v0 = *(const float2*)(x0 + col);
            float2 v1 = *(const float2*)(x1 + col);
            ymc[n][g][0] = v0.x; ymc[n][g][1] = v0.y;
            ymc[n][g][2] = v1.x; ymc[n][g][3] = v1.y;
        }
        int colr = 128 + 8 * e + colb;
        float2 v0 = *(const float2*)(x0 + colr);
        float2 v1 = *(const float2*)(x1 + colr);
        ymr[g][0] = v0.x; ymr[g][1] = v0.y; ymr[g][2] = v1.x; ymr[g][3] = v1.y;
#pragma unroll
        for (int n = 0; n < 2; ++n) {
            uint2 f;
            f.x = pbf(ymc[n][g][0], ymc[n][g][1]);
            f.y = pbf(ymc[n][g][2], ymc[n][g][3]);
            *(uint2*)(ybg[g] + 2 * (2 * e + n)) = f;
        }
        uint2 fr;
        fr.x = pbf(ymr[g][0], ymr[g][1]);
        fr.y = pbf(ymr[g][2], ymr[g][3]);
        *(uint2*)(ybg[g] + 2 * (16 + e)) = fr;
    }
    __syncthreads();

    float a1[3][4], a2c[2][4], a2r[4];

    auto mma1 = [&](const unsigned* yb) {
#pragma unroll
        for (int n = 0; n < 3; ++n)
#pragma unroll
            for (int v = 0; v < 4; ++v) a1[n][v] = 0.0f;
#pragma unroll
        for (int k = 0; k < 12; ++k) {
            uint4 av = *(const uint4*)(yb + 4 * k);
            MMA(a1[0], av.x, av.y, av.z, av.w, B1[k][0][0], B1[k][0][1]);
            MMA(a1[1], av.x, av.y, av.z, av.w, B1[k][1][0], B1[k][1][1]);
            MMA(a1[2], av.x, av.y, av.z, av.w, B1[k][2][0], B1[k][2][1]);
        }
    };
    auto pubh = [&](unsigned* hb) {
#pragma unroll
        for (int n = 0; n < 3; ++n) {
            uint2 f;
            f.x = pbf(fmaxf(a1[n][0] + bc1[n].x, 0.0f),
                      fmaxf(a1[n][1] + bc1[n].y, 0.0f));
            f.y = pbf(fmaxf(a1[n][2] + bc1[n].x, 0.0f),
                      fmaxf(a1[n][3] + bc1[n].y, 0.0f));
            *(uint2*)(hb + 2 * (3 * e + n)) = f;
        }
    };
    auto mma2 = [&](const unsigned* hb) {
#pragma unroll
        for (int n = 0; n < 2; ++n)
#pragma unroll
            for (int v = 0; v < 4; ++v) { a2c[n][v] = 0.0f; }
#pragma unroll
        for (int v = 0; v < 4; ++v) a2r[v] = 0.0f;
#pragma unroll
        for (int k = 0; k < 8; ++k) {
            uint4 av = *(const uint4*)(hb + 4 * k);
            MMA(a2c[0], av.x, av.y, av.z, av.w, B2c[k][0][0], B2c[k][0][1]);
            MMA(a2c[1], av.x, av.y, av.z, av.w, B2c[k][1][0], B2c[k][1][1]);
        }
#pragma unroll
        for (int k = 0; k < 4; ++k) {
            uint4 av = *(const uint4*)(hb + 32 + 4 * k);
            MMA(a2r, av.x, av.y, av.z, av.w, B2r[k][0], B2r[k][1]);
        }
    };
    auto epi = [&](int g, int t, unsigned* yb) {
        float* o0 = out + (size_t)rows[g] * 12288 + t * 192;
        float* o1 = o0 + 8 * 12288;
#pragma unroll
        for (int n = 0; n < 2; ++n) {   // complex pairs: even col = mu, odd = omega
            int col = 8 * (2 * e + n) + colb;
            float zm0 = fmaf(a2c[n][0], 0.01f, bc2s[n].x);
            float zo0 = fmaf(a2c[n][1], 0.01f, bc2s[n].y);
            float e0 = exp3(zm0);
            float q0 = zo0 * zo0;
            float s0 = zo0 * (1.0f - q0 * 0.16666667f);
            float c0 = 1.0f - q0 * (0.5f - q0 * (1.0f / 24.0f));
            float ye = ymc[n][g][0], yo = ymc[n][g][1];
            ymc[n][g][0] = e0 * (c0 * ye - s0 * yo);
            ymc[n][g][1] = e0 * (s0 * ye + c0 * yo);
            float zm1 = fmaf(a2c[n][2], 0.01f, bc2s[n].x);
            float zo1 = fmaf(a2c[n][3], 0.01f, bc2s[n].y);
            float e1 = exp3(zm1);
            float q1 = zo1 * zo1;
            float s1 = zo1 * (1.0f - q1 * 0.16666667f);
            float c1 = 1.0f - q1 * (0.5f - q1 * (1.0f / 24.0f));
            ye = ymc[n][g][2]; yo = ymc[n][g][3];
            ymc[n][g][2] = e1 * (c1 * ye - s1 * yo);
            ymc[n][g][3] = e1 * (s1 * ye + c1 * yo);
            *(float2*)(o0 + col) = make_float2(ymc[n][g][0], ymc[n][g][1]);
            *(float2*)(o1 + col) = make_float2(ymc[n][g][2], ymc[n][g][3]);
            uint2 f;
            f.x = pbf(ymc[n][g][0], ymc[n][g][1]);
            f.y = pbf(ymc[n][g][2], ymc[n][g][3]);
            *(uint2*)(yb + 2 * (2 * e + n)) = f;
        }
        {   // real diagonal
            int col = 128 + 8 * e + colb;
            ymr[g][0] *= exp3(fmaf(a2r[0], 0.01f, br2s.x));
            ymr[g][1] *= exp3(fmaf(a2r[1], 0.01f, br2s.y));
            ymr[g][2] *= exp3(fmaf(a2r[2], 0.01f, br2s.x));
            ymr[g][3] *= exp3(fmaf(a2r[3], 0.01f, br2s.y));
            *(float2*)(o0 + col) = make_float2(ymr[g][0], ymr[g][1]);
            *(float2*)(o1 + col) = make_float2(ymr[g][2], ymr[g][3]);
            uint2 f;
            f.x = pbf(ymr[g][0], ymr[g][1]);
            f.y = pbf(ymr[g][2], ymr[g][3]);
            *(uint2*)(yb + 2 * (16 + e)) = f;
        }
    };

    // ---- prologue: h(g0) for t=0 ----
    mma1(ybg[0]);
    pubh(hbg[0]);
    __syncthreads();

#pragma unroll 1
    for (int t = 0; t < 64; ++t) {
        // section 1: consume H0, Y1; produce Y0 (t), H1 (t)
        mma2(hbg[0]);
        mma1(ybg[1]);
        epi(0, t, ybg[0]);
        pubh(hbg[1]);
        __syncthreads();
        // section 2: consume H1, Y0; produce Y1 (t), H0 (t+1)
        mma2(hbg[1]);
        mma1(ybg[0]);
        epi(1, t, ybg[1]);
        pubh(hbg[0]);
        __syncthreads();
    }
}

extern "C" void kernel_launch(void* const* d_in, const int* in_sizes, int n_in,
                              void* d_out, int out_size)
{
    (void)in_sizes; (void)n_in; (void)out_size;
    cudaFuncSetAttribute(koopman_pl_kernel,
                         cudaFuncAttributeMaxDynamicSharedMemorySize, SMEM_BYTES);
    koopman_pl_kernel<<<128, 256, SMEM_BYTES>>>(
        (const float*)d_in[0],
        (const float*)d_in[1], (const float*)d_in[2],
        (const float*)d_in[3], (const float*)d_in[4],
        (const float*)d_in[5], (const float*)d_in[6],
        (const float*)d_in[7], (const float*)d_in[8],
        (float*)d_out);
}

// round 12
// speedup vs baseline: 1.1338x; 1.1338x over previous
#include <cuda_runtime.h>
#include <cuda_bf16.h>
#include <cstdint>

// Koopman rollout via warp-level HMMA, register-resident weights, 12 warps/CTA.
// 128 CTAs x 384 threads; CTA owns 32 rows (2 row-groups x 16).
// Feature split across 12 warps (3 warps/SMSP for latency hiding):
//   MMA1 (N=192, 24 n-tiles): warp w owns tiles {2w, 2w+1}      -> 48 MMA/step
//   MMA2: warps 0-7 own complex tiles {2w,2w+1} (K=128)         -> 32 MMA/step
//         warps 8-11 own real tiles (K=64)                      -> 16 MMA/step
// B-fragments (<=80 regs) loaded once via ldmatrix; inner loop has no weight
// SMEM reads. Activation frags exchanged via per-lane SMEM rows (LDS.128).
// Transcendentals are degree-3 Taylor polys (|arg| <= ~0.02).

#define SMEM_BYTES 148992u
#define OFF_W1  0u        // [192 n][k stride 400B bf16]   76800 B (init staging)
#define OFF_W2C 76800u    // [128 n][k stride 272B]        34816 B (init staging)
#define OFF_W2R 111616u   // [64 n][k stride 144B]          9216 B (init staging)
#define OFF_B1  120832u   // f32[192]
#define OFF_B2  121600u   // f32[192]
#define OFF_YB  122368u   // y frags: [2 grp][32 lane][52 u32]  13312 B
#define OFF_HB  135680u   // h1 frags: same                      13312 B

__device__ __forceinline__ unsigned smem_u32(const void* p) {
    unsigned a;
    asm("{ .reg .u64 t; cvta.to.shared.u64 t, %1; cvt.u32.u64 %0, t; }"
        : "=r"(a) : "l"(p));
    return a;
}
__device__ __forceinline__ unsigned pbf(float lo, float hi) {
    unsigned r;
    asm("cvt.rn.bf16x2.f32 %0, %1, %2;" : "=r"(r) : "f"(hi), "f"(lo));
    return r;
}
// exp(z) for tiny z, degree-3 Taylor
__device__ __forceinline__ float exp3(float z) {
    return 1.0f + z * (1.0f + z * (0.5f + z * 0.16666667f));
}

#define LDSM4(r0, r1, r2, r3, a) \
    asm volatile("ldmatrix.sync.aligned.m8n8.x4.shared.b16 {%0,%1,%2,%3}, [%4];" \
                 : "=r"(r0), "=r"(r1), "=r"(r2), "=r"(r3) : "r"(a))

#define MMA(d, a0, a1, a2, a3, b0, b1) \
    asm volatile("mma.sync.aligned.m16n8k16.row.col.f32.bf16.bf16.f32 " \
                 "{%0,%1,%2,%3},{%4,%5,%6,%7},{%8,%9},{%0,%1,%2,%3};" \
                 : "+f"((d)[0]), "+f"((d)[1]), "+f"((d)[2]), "+f"((d)[3]) \
                 : "r"(a0), "r"(a1), "r"(a2), "r"(a3), "r"(b0), "r"(b1))

__global__ void __launch_bounds__(384, 1)
koopman_w12_kernel(const float* __restrict__ x,
                   const float* __restrict__ cW1, const float* __restrict__ cb1,
                   const float* __restrict__ cW2, const float* __restrict__ cb2,
                   const float* __restrict__ rW1, const float* __restrict__ rb1,
                   const float* __restrict__ rW2, const float* __restrict__ rb2,
                   float* __restrict__ out)
{
    extern __shared__ unsigned char smem[];
    const unsigned sb = smem_u32(smem);
    const int tid = threadIdx.x;
    const int lane = tid & 31;
    const int w = tid >> 5;            // warp 0..11
    const bool isc = (w < 8);          // complex-head warp?

    float* b1f = (float*)(smem + OFF_B1);
    float* b2f = (float*)(smem + OFF_B2);

    // ---- one-time: weights -> bf16 SMEM (staging for ldmatrix) ----
    for (int idx = tid; idx < 192 * 96; idx += 384) {
        int n = idx / 96, k = 2 * (idx - n * 96);
        const float* s = (n < 128) ? (cW1 + n * 192 + k) : (rW1 + (n - 128) * 192 + k);
        *(unsigned*)(smem + OFF_W1 + n * 400 + k * 2) = pbf(s[0], s[1]);
    }
    for (int idx = tid; idx < 128 * 64; idx += 384) {
        int n = idx >> 6, k = 2 * (idx & 63);
        *(unsigned*)(smem + OFF_W2C + n * 272 + k * 2) =
            pbf(cW2[n * 128 + k], cW2[n * 128 + k + 1]);
    }
    for (int idx = tid; idx < 64 * 32; idx += 384) {
        int n = idx >> 5, k = 2 * (idx & 31);
        *(unsigned*)(smem + OFF_W2R + n * 144 + k * 2) =
            pbf(rW2[n * 64 + k], rW2[n * 64 + k + 1]);
    }
    for (int i = tid; i < 192; i += 384) {
        b1f[i] = (i < 128) ? cb1[i] : rb1[i - 128];
        b2f[i] = (i < 128) ? cb2[i] : rb2[i - 128];
    }
    __syncthreads();

    // ---- per-lane constants ----
    const int colb = 2 * (lane & 3);
    const int lrow = (lane & 7) + ((lane >> 4) << 3);
    const unsigned lkb = ((lane >> 3) & 1) * 16;

    // ---- persistent B-fragments in registers ----
    unsigned B1[12][2][2];      // MMA1: 2 owned n-tiles, 12 k-iters
    unsigned B2[8][2][2];       // MMA2: complex (8 k) or real (4 k, rest unused)
    {
        const unsigned aW1 = sb + OFF_W1 + w * 16 * 400 + lrow * 400 + lkb;
#pragma unroll
        for (int k = 0; k < 12; ++k)
            LDSM4(B1[k][0][0], B1[k][0][1], B1[k][1][0], B1[k][1][1], aW1 + k * 32);
        if (isc) {
            const unsigned aW2 = sb + OFF_W2C + w * 16 * 272 + lrow * 272 + lkb;
#pragma unroll
            for (int k = 0; k < 8; ++k)
                LDSM4(B2[k][0][0], B2[k][0][1], B2[k][1][0], B2[k][1][1], aW2 + k * 32);
        } else {
            const unsigned aW2 = sb + OFF_W2R + (w - 8) * 16 * 144 + lrow * 144 + lkb;
#pragma unroll
            for (int k = 0; k < 4; ++k)
                LDSM4(B2[k][0][0], B2[k][0][1], B2[k][1][0], B2[k][1][1], aW2 + k * 32);
        }
    }

    // ---- owned columns / bias regs ----
    const int c1base = 16 * w;                               // MMA1 cols 16w..16w+15
    const int c2base = isc ? 16 * w : 128 + 16 * (w - 8);    // MMA2 output cols
    const int ybo = isc ? 4 * w : 32 + 4 * (w - 8);          // y-frag u32 offset
    float2 bc1[2], bc2s[2];
#pragma unroll
    for (int n = 0; n < 2; ++n) {
        bc1[n] = *(const float2*)(b1f + c1base + 8 * n + colb);
        float2 b = *(const float2*)(b2f + c2base + 8 * n + colb);
        bc2s[n] = make_float2(0.01f * b.x, 0.01f * b.y);
    }

    // ---- frag exchange rows (52-u32 lane stride: conflict-free LDS.128) ----
    unsigned* ybg[2];
    unsigned* hbg[2];
#pragma unroll
    for (int g = 0; g < 2; ++g) {
        ybg[g] = (unsigned*)(smem + OFF_YB) + (g * 32 + lane) * 52;
        hbg[g] = (unsigned*)(smem + OFF_HB) + (g * 32 + lane) * 52;
    }

    // ---- y master state: 2 owned output tiles x 2 groups ----
    int rows[2];
    rows[0] = blockIdx.x * 32 + (lane >> 2);
    rows[1] = rows[0] + 16;
    float ym[2][2][4];   // [tile][group][r0c0, r0c1, r1c0, r1c1]
#pragma unroll
    for (int g = 0; g < 2; ++g) {
        const float* x0 = x + (size_t)rows[g] * 12288;
        const float* x1 = x0 + 8 * 12288;
        uint4 f;
#pragma unroll
        for (int n = 0; n < 2; ++n) {
            int col = c2base + 8 * n + colb;
            float2 v0 = *(const float2*)(x0 + col);
            float2 v1 = *(const float2*)(x1 + col);
            ym[n][g][0] = v0.x; ym[n][g][1] = v0.y;
            ym[n][g][2] = v1.x; ym[n][g][3] = v1.y;
        }
        f.x = pbf(ym[0][g][0], ym[0][g][1]);
        f.y = pbf(ym[0][g][2], ym[0][g][3]);
        f.z = pbf(ym[1][g][0], ym[1][g][1]);
        f.w = pbf(ym[1][g][2], ym[1][g][3]);
        *(uint4*)(ybg[g] + ybo) = f;
    }
    __syncthreads();

    float a1[2][4], a2[2][4];

    auto mma1 = [&](const unsigned* yb) {
#pragma unroll
        for (int n = 0; n < 2; ++n)
#pragma unroll
            for (int v = 0; v < 4; ++v) a1[n][v] = 0.0f;
#pragma unroll
        for (int k = 0; k < 12; ++k) {
            uint4 av = *(const uint4*)(yb + 4 * k);
            MMA(a1[0], av.x, av.y, av.z, av.w, B1[k][0][0], B1[k][0][1]);
            MMA(a1[1], av.x, av.y, av.z, av.w, B1[k][1][0], B1[k][1][1]);
        }
    };
    auto pubh = [&](unsigned* hb) {
        uint4 f;
        f.x = pbf(fmaxf(a1[0][0] + bc1[0].x, 0.0f), fmaxf(a1[0][1] + bc1[0].y, 0.0f));
        f.y = pbf(fmaxf(a1[0][2] + bc1[0].x, 0.0f), fmaxf(a1[0][3] + bc1[0].y, 0.0f));
        f.z = pbf(fmaxf(a1[1][0] + bc1[1].x, 0.0f), fmaxf(a1[1][1] + bc1[1].y, 0.0f));
        f.w = pbf(fmaxf(a1[1][2] + bc1[1].x, 0.0f), fmaxf(a1[1][3] + bc1[1].y, 0.0f));
        *(uint4*)(hb + 4 * w) = f;
    };
    auto mma2 = [&](const unsigned* hb) {
#pragma unroll
        for (int n = 0; n < 2; ++n)
#pragma unroll
            for (int v = 0; v < 4; ++v) a2[n][v] = 0.0f;
        if (isc) {
#pragma unroll
            for (int k = 0; k < 8; ++k) {
                uint4 av = *(const uint4*)(hb + 4 * k);
                MMA(a2[0], av.x, av.y, av.z, av.w, B2[k][0][0], B2[k][0][1]);
                MMA(a2[1], av.x, av.y, av.z, av.w, B2[k][1][0], B2[k][1][1]);
            }
        } else {
#pragma unroll
            for (int k = 0; k < 4; ++k) {
                uint4 av = *(const uint4*)(hb + 32 + 4 * k);
                MMA(a2[0], av.x, av.y, av.z, av.w, B2[k][0][0], B2[k][0][1]);
                MMA(a2[1], av.x, av.y, av.z, av.w, B2[k][1][0], B2[k][1][1]);
            }
        }
    };
    auto epi = [&](int g, int t, unsigned* yb) {
        float* o0 = out + (size_t)rows[g] * 12288 + t * 192;
        float* o1 = o0 + 8 * 12288;
        if (isc) {
#pragma unroll
            for (int n = 0; n < 2; ++n) {   // complex: even col = mu, odd = omega
                float zm0 = fmaf(a2[n][0], 0.01f, bc2s[n].x);
                float zo0 = fmaf(a2[n][1], 0.01f, bc2s[n].y);
                float e0 = exp3(zm0);
                float q0 = zo0 * zo0;
                float s0 = zo0 * (1.0f - q0 * 0.16666667f);
                float c0 = 1.0f - q0 * (0.5f - q0 * (1.0f / 24.0f));
                float ye = ym[n][g][0], yo = ym[n][g][1];
                ym[n][g][0] = e0 * (c0 * ye - s0 * yo);
                ym[n][g][1] = e0 * (s0 * ye + c0 * yo);
                float zm1 = fmaf(a2[n][2], 0.01f, bc2s[n].x);
                float zo1 = fmaf(a2[n][3], 0.01f, bc2s[n].y);
                float e1 = exp3(zm1);
                float q1 = zo1 * zo1;
                float s1 = zo1 * (1.0f - q1 * 0.16666667f);
                float c1 = 1.0f - q1 * (0.5f - q1 * (1.0f / 24.0f));
                ye = ym[n][g][2]; yo = ym[n][g][3];
                ym[n][g][2] = e1 * (c1 * ye - s1 * yo);
                ym[n][g][3] = e1 * (s1 * ye + c1 * yo);
            }
        } else {
#pragma unroll
            for (int n = 0; n < 2; ++n) {   // real diagonal
                ym[n][g][0] *= exp3(fmaf(a2[n][0], 0.01f, bc2s[n].x));
                ym[n][g][1] *= exp3(fmaf(a2[n][1], 0.01f, bc2s[n].y));
                ym[n][g][2] *= exp3(fmaf(a2[n][2], 0.01f, bc2s[n].x));
                ym[n][g][3] *= exp3(fmaf(a2[n][3], 0.01f, bc2s[n].y));
            }
        }
#pragma unroll
        for (int n = 0; n < 2; ++n) {
            int col = c2base + 8 * n + colb;
            *(float2*)(o0 + col) = make_float2(ym[n][g][0], ym[n][g][1]);
            *(float2*)(o1 + col) = make_float2(ym[n][g][2], ym[n][g][3]);
        }
        uint4 f;
        f.x = pbf(ym[0][g][0], ym[0][g][1]);
        f.y = pbf(ym[0][g][2], ym[0][g][3]);
        f.z = pbf(ym[1][g][0], ym[1][g][1]);
        f.w = pbf(ym[1][g][2], ym[1][g][3]);
        *(uint4*)(yb + ybo) = f;
    };

    // ---- prologue: h(g0) for t=0 ----
    mma1(ybg[0]);
    pubh(hbg[0]);
    __syncthreads();

#pragma unroll 1
    for (int t = 0; t < 64; ++t) {
        // section 1: consume H0, Y1; produce Y0 (t), H1 (t)
        mma2(hbg[0]);
        mma1(ybg[1]);
        epi(0, t, ybg[0]);
        pubh(hbg[1]);
        __syncthreads();
        // section 2: consume H1, Y0; produce Y1 (t), H0 (t+1)
        mma2(hbg[1]);
        mma1(ybg[0]);
        epi(1, t, ybg[1]);
        pubh(hbg[0]);
        __syncthreads();
    }
}

extern "C" void kernel_launch(void* const* d_in, const int* in_sizes, int n_in,
                              void* d_out, int out_size)
{
    (void)in_sizes; (void)n_in; (void)out_size;
    cudaFuncSetAttribute(koopman_w12_kernel,
                         cudaFuncAttributeMaxDynamicSharedMemorySize, SMEM_BYTES);
    koopman_w12_kernel<<<128, 384, SMEM_BYTES>>>(
        (const float*)d_in[0],
        (const float*)d_in[1], (const float*)d_in[2],
        (const float*)d_in[3], (const float*)d_in[4],
        (const float*)d_in[5], (const float*)d_in[6],
        (const float*)d_in[7], (const float*)d_in[8],
        (float*)d_out);
}